// round 10
// baseline (speedup 1.0000x reference)
#include <cuda_runtime.h>
#include <math.h>
#include <stdint.h>

#define HIDDEN 1024
#define HEADS  8
#define HEAD   128
#define BATCH  512

__device__ __forceinline__ float dot4(float4 a, float4 b) {
    return a.x*b.x + a.y*b.y + a.z*b.z + a.w*b.w;
}

// 256-bit global load, streaming (evict-first) policy.
__device__ __forceinline__ void ldg8_cs(const float* p, float4& a, float4& b) {
    asm volatile("ld.global.cs.v8.f32 {%0,%1,%2,%3,%4,%5,%6,%7}, [%8];"
        : "=f"(a.x), "=f"(a.y), "=f"(a.z), "=f"(a.w),
          "=f"(b.x), "=f"(b.y), "=f"(b.z), "=f"(b.w)
        : "l"(p));
}
// 256-bit global store (default write-back; r8 showed policy-insensitive).
__device__ __forceinline__ void stg8_wb(float* p, float4 a, float4 b) {
    asm volatile("st.global.v8.f32 [%0], {%1,%2,%3,%4,%5,%6,%7,%8};"
        :: "l"(p),
           "f"(a.x), "f"(a.y), "f"(a.z), "f"(a.w),
           "f"(b.x), "f"(b.y), "f"(b.z), "f"(b.w)
        : "memory");
}
// 16-byte async copy to shared, L2-only (bypass L1): register-free prefetch.
__device__ __forceinline__ void cp_async16(void* dst_smem, const float* src) {
    unsigned int d = (unsigned int)__cvta_generic_to_shared(dst_smem);
    asm volatile("cp.async.cg.shared.global [%0], [%1], 16;" :: "r"(d), "l"(src));
}

// ---------------------------------------------------------------------------
// Fully fused gate GEMV + mLSTM step + GroupNorm. One (b,h) tile per block,
// 256 threads, 4 CTAs/SM.
// Read front-loading: at kernel ENTRY 7 of 8 iterations' cell reads are
// issued -- 3 into a register ring (plus iter 7 reloading slot 0 at i=0) and
// iterations 3-6 via cp.async into a 32KB smem staging buffer (zero register
// cost). The gate GEMV prologue and the epilogue of the previous wave are
// thus bridged by in-flight DRAM reads.
// ---------------------------------------------------------------------------
__global__ __launch_bounds__(256, 4) void mlstm_fused_kernel(
    const float* __restrict__ q, const float* __restrict__ k,
    const float* __restrict__ v, const float* __restrict__ cell,
    const float* __restrict__ norm, const float* __restrict__ maxs,
    const float* __restrict__ Wi, const float* __restrict__ bi,
    const float* __restrict__ Wf, const float* __restrict__ bf,
    const float* __restrict__ gamma, const float* __restrict__ beta,
    float* __restrict__ out, float* __restrict__ cell_out,
    float* __restrict__ norm_out, float* __restrict__ max_out)
{
    int bh   = blockIdx.x;
    int b    = bh >> 3;
    int h    = bh & 7;
    int tid  = threadIdx.x;
    int lane = tid & 31;
    int warp = tid >> 5;

    __shared__ __align__(16) float q_s[HEAD];
    __shared__ __align__(16) float k_s[HEAD];
    __shared__ __align__(16) float v_s[HEAD];
    __shared__ __align__(16) float4 spf[4][2][256];  // 32KB cp.async staging (iters 3-6)
    __shared__ __align__(16) float4 snum8[256][2];   // per-thread float8 partials
    __shared__ float pig[8], pfg[8], pq[4], pm[4], pv[4];

    const float rsqrtD = 0.08838834764831845f;  // 1/sqrt(128)

    // ---- cell addressing: row0 = 2*warp + (lane>>4), col octet = lane&15 ---
    int rsub = (warp << 1) + (lane >> 4);        // 0..15 within each 16-row band
    int c8   = lane & 15;                        // column octet (8 floats)
    const float* cbase = cell + (size_t)bh * HEAD * HEAD + rsub * HEAD + c8 * 8;
    float* obase = cell_out
                 ? cell_out + (size_t)bh * HEAD * HEAD + rsub * HEAD + c8 * 8
                 : (float*)0;

    // ---- front-load reads: ring (iters 0-2) + cp.async (iters 3-6) ---------
    float4 cva[3], cvb[3];
    #pragma unroll
    for (int i = 0; i < 3; ++i)
        ldg8_cs(cbase + i * 16 * HEAD, cva[i], cvb[i]);
    #pragma unroll
    for (int i = 0; i < 4; ++i) {
        cp_async16(&spf[i][0][tid], cbase + (i + 3) * 16 * HEAD);
        cp_async16(&spf[i][1][tid], cbase + (i + 3) * 16 * HEAD + 4);
    }
    asm volatile("cp.async.commit_group;" ::: "memory");

    // ---- gate pre-activations: igp/fgp = qkv_row . W[h] + b[h] -------------
    const float4* qrow = (const float4*)(q + (size_t)b * HIDDEN);
    const float4* krow = (const float4*)(k + (size_t)b * HIDDEN);
    const float4* vrow = (const float4*)(v + (size_t)b * HIDDEN);
    const float4* Wi4  = (const float4*)Wi + (size_t)h * 768;
    const float4* Wf4  = (const float4*)Wf + (size_t)h * 768;

    float4 xq = qrow[tid];
    float4 xk = krow[tid];
    float4 xv = vrow[tid];

    float ai = dot4(xq, Wi4[tid]) + dot4(xk, Wi4[256 + tid]) + dot4(xv, Wi4[512 + tid]);
    float af = dot4(xq, Wf4[tid]) + dot4(xk, Wf4[256 + tid]) + dot4(xv, Wf4[512 + tid]);

    // warp h already holds the head slice in registers -> stash to smem
    if (warp == h) {
        ((float4*)q_s)[lane] = xq;
        float4 sk;
        sk.x = xk.x * rsqrtD; sk.y = xk.y * rsqrtD;
        sk.z = xk.z * rsqrtD; sk.w = xk.w * rsqrtD;
        ((float4*)k_s)[lane] = sk;
        ((float4*)v_s)[lane] = xv;
    }

    #pragma unroll
    for (int off = 16; off > 0; off >>= 1) {
        ai += __shfl_xor_sync(0xffffffffu, ai, off);
        af += __shfl_xor_sync(0xffffffffu, af, off);
    }
    if (lane == 0) { pig[warp] = ai; pfg[warp] = af; }
    __syncthreads();                                   // sync #1

    float igp = bi[h], fgp = bf[h];
    #pragma unroll
    for (int w = 0; w < 8; ++w) { igp += pig[w]; fgp += pfg[w]; }

    float log_f = fminf(fgp, 0.f) - log1pf(expf(-fabsf(fgp)));   // log sigmoid
    float m_old = maxs[bh];
    float m_new = fmaxf(igp, m_old + log_f);
    float i_g   = expf(igp - m_new);
    float f_g   = expf(log_f + m_old - m_new);

    if (tid == 0 && max_out) max_out[bh] = m_new;

    // ---- norm update + qn partials (reduction deferred to sync #2) ---------
    if (tid < HEAD) {
        float nn = fmaf(f_g, norm[(size_t)bh * HEAD + tid], i_g * k_s[tid]);
        if (norm_out) norm_out[(size_t)bh * HEAD + tid] = nn;
        float qn = q_s[tid] * nn;
        #pragma unroll
        for (int off = 16; off > 0; off >>= 1)
            qn += __shfl_xor_sync(0xffffffffu, qn, off);
        if (lane == 0) pq[warp] = qn;
    }

    // ---- main stream: 8 iterations of 16 rows ------------------------------
    float4 vlo = ((const float4*)v_s)[c8 * 2];
    float4 vhi = ((const float4*)v_s)[c8 * 2 + 1];
    float4 numa = make_float4(0.f, 0.f, 0.f, 0.f);
    float4 numb = make_float4(0.f, 0.f, 0.f, 0.f);

    #pragma unroll
    for (int i = 0; i < 8; ++i) {
        if (i == 3)
            asm volatile("cp.async.wait_group 0;" ::: "memory");
        float4 ca, cb;
        if (i < 3)      { ca = cva[i]; cb = cvb[i]; }
        else if (i < 7) { ca = spf[i - 3][0][tid]; cb = spf[i - 3][1][tid]; }
        else            { ca = cva[0]; cb = cvb[0]; }
        if (i == 0)     // reload ring slot 0 with iter 7 (read-before-write above)
            ldg8_cs(cbase + 7 * 16 * HEAD, cva[0], cvb[0]);

        int r = i * 16 + rsub;
        float a = i_g * k_s[r];
        float4 cna, cnb;
        cna.x = fmaf(f_g, ca.x, a * vlo.x);
        cna.y = fmaf(f_g, ca.y, a * vlo.y);
        cna.z = fmaf(f_g, ca.z, a * vlo.z);
        cna.w = fmaf(f_g, ca.w, a * vlo.w);
        cnb.x = fmaf(f_g, cb.x, a * vhi.x);
        cnb.y = fmaf(f_g, cb.y, a * vhi.y);
        cnb.z = fmaf(f_g, cb.z, a * vhi.z);
        cnb.w = fmaf(f_g, cb.w, a * vhi.w);
        if (obase) stg8_wb(obase + i * 16 * HEAD, cna, cnb);
        float qr = q_s[r];
        numa.x = fmaf(qr, cna.x, numa.x);
        numa.y = fmaf(qr, cna.y, numa.y);
        numa.z = fmaf(qr, cna.z, numa.z);
        numa.w = fmaf(qr, cna.w, numa.w);
        numb.x = fmaf(qr, cnb.x, numb.x);
        numb.y = fmaf(qr, cnb.y, numb.y);
        numb.z = fmaf(qr, cnb.z, numb.z);
        numb.w = fmaf(qr, cnb.w, numb.w);
    }

    // ---- numerator reduction: 16 contributor threads per column ------------
    snum8[tid][0] = numa;
    snum8[tid][1] = numb;
    __syncthreads();                                   // sync #2 (covers pq)

    // thread tid<128 owns output column tid: contributors are tids {g+16j},
    // g = tid>>3; element index e = tid&7 inside the float8.
    float numc = 0.f;
    if (tid < HEAD) {
        int g = tid >> 3;
        int e = tid & 7;
        #pragma unroll
        for (int j = 0; j < 16; ++j)
            numc += ((const float*)&snum8[g + 16 * j][0])[e];
    }

    // ---- denominator + out_pre + GN stats -----------------------------------
    float o = 0.f, so = 0.f, so2 = 0.f;
    if (tid < HEAD) {
        float qn    = pq[0] + pq[1] + pq[2] + pq[3];
        float denom = fmaxf(fabsf(qn), expf(-m_new)) + 1e-6f;
        o   = numc / denom;
        so  = o;
        so2 = o * o;
    }
    #pragma unroll
    for (int off = 16; off > 0; off >>= 1) {
        so  += __shfl_xor_sync(0xffffffffu, so,  off);
        so2 += __shfl_xor_sync(0xffffffffu, so2, off);
    }
    if (tid < HEAD && lane == 0) { pm[warp] = so; pv[warp] = so2; }
    __syncthreads();                                   // sync #3

    if (tid < HEAD) {
        float mu   = (pm[0] + pm[1] + pm[2] + pm[3]) * (1.f / HEAD);
        float var  = (pv[0] + pv[1] + pv[2] + pv[3]) * (1.f / HEAD) - mu * mu;
        float rstd = rsqrtf(var + 1e-5f);
        int ch = h * HEAD + tid;
        out[(size_t)b * HIDDEN + ch] = (o - mu) * rstd * gamma[ch] + beta[ch];
    }
}

// ---------------------------------------------------------------------------
extern "C" void kernel_launch(void* const* d_in, const int* in_sizes, int n_in,
                              void* d_out, int out_size)
{
    const float* q     = (const float*)d_in[0];
    const float* k     = (const float*)d_in[1];
    const float* v     = (const float*)d_in[2];
    const float* cell  = (const float*)d_in[3];
    const float* norm  = (const float*)d_in[4];
    const float* maxs  = (const float*)d_in[5];
    const float* Wi    = (const float*)d_in[6];
    const float* bi    = (const float*)d_in[7];
    const float* Wf    = (const float*)d_in[8];
    const float* bf    = (const float*)d_in[9];
    const float* gamma = (const float*)d_in[10];
    const float* beta  = (const float*)d_in[11];

    float* out = (float*)d_out;

    const size_t OUT_N  = (size_t)BATCH * HIDDEN;                 // 524288
    const size_t CELL_N = (size_t)BATCH * HEADS * HEAD * HEAD;    // 67108864
    const size_t NORM_N = (size_t)BATCH * HEADS * HEAD;           // 524288
    const size_t MAX_N  = (size_t)BATCH * HEADS;                  // 4096

    float* cell_out = 0;
    float* norm_out = 0;
    float* max_out  = 0;
    if ((size_t)out_size >= OUT_N + CELL_N + NORM_N + MAX_N) {
        cell_out = out + OUT_N;
        norm_out = cell_out + CELL_N;
        max_out  = norm_out + NORM_N;
    }

    mlstm_fused_kernel<<<BATCH * HEADS, 256>>>(q, k, v, cell, norm, maxs,
                                               Wi, bi, Wf, bf, gamma, beta,
                                               out, cell_out, norm_out, max_out);
}

// round 11
// speedup vs baseline: 1.1156x; 1.1156x over previous
#include <cuda_runtime.h>
#include <math.h>

#define HIDDEN 1024
#define HEADS  8
#define HEAD   128
#define BATCH  512

__device__ __forceinline__ float dot4(float4 a, float4 b) {
    return a.x*b.x + a.y*b.y + a.z*b.z + a.w*b.w;
}

// ---------------------------------------------------------------------------
// Single fully fused kernel: gate GEMV + mLSTM step + GroupNorm.
// One block per (b,h), 256 threads, 4 CTAs/SM. (Round-4 structure: best of
// six structural variants; all viable configs plateau at ~79% DRAM, which is
// the HW ceiling for this 50/50 read+write stream.)
//   - first 8 cell-row loads issued at kernel ENTRY (independent of gates),
//     so the gate GEMV + reductions hide under cell-load latency
//   - main loop is a rolling depth-8 software pipeline: consume one row,
//     immediately issue the load 8 rows ahead -> constant MLP=8 per warp
// ---------------------------------------------------------------------------
__global__ __launch_bounds__(256) void mlstm_fused_kernel(
    const float* __restrict__ q, const float* __restrict__ k,
    const float* __restrict__ v, const float* __restrict__ cell,
    const float* __restrict__ norm, const float* __restrict__ maxs,
    const float* __restrict__ Wi, const float* __restrict__ bi,
    const float* __restrict__ Wf, const float* __restrict__ bf,
    const float* __restrict__ gamma, const float* __restrict__ beta,
    float* __restrict__ out, float* __restrict__ cell_out,
    float* __restrict__ norm_out, float* __restrict__ max_out)
{
    int bh   = blockIdx.x;
    int b    = bh >> 3;
    int h    = bh & 7;
    int tid  = threadIdx.x;
    int lane = tid & 31;
    int warp = tid >> 5;

    __shared__ __align__(16) float q_s[HEAD];
    __shared__ __align__(16) float k_s[HEAD];
    __shared__ __align__(16) float v_s[HEAD];
    __shared__ float4 snum[256];
    __shared__ float pig[8], pfg[8], pq[4], pm[4], pv[4];

    const float rsqrtD = 0.08838834764831845f;  // 1/sqrt(128)

    // ---- cell tile pointers: warp = row-group, lane = float4 column --------
    const float4* cp = (const float4*)(cell + (size_t)bh * HEAD * HEAD)
                       + warp * 32 + lane;
    float4* op = cell_out
               ? (float4*)(cell_out + (size_t)bh * HEAD * HEAD) + warp * 32 + lane
               : (float4*)0;

    // ---- prefetch first 8 cell rows BEFORE the gate GEMV -------------------
    float4 cv[8];
    #pragma unroll
    for (int i = 0; i < 8; ++i)
        cv[i] = __ldcs(cp + i * 256);

    // ---- gate pre-activations: igp/fgp = qkv_row . W[h] + b[h] -------------
    const float4* qrow = (const float4*)(q + (size_t)b * HIDDEN);
    const float4* krow = (const float4*)(k + (size_t)b * HIDDEN);
    const float4* vrow = (const float4*)(v + (size_t)b * HIDDEN);
    const float4* Wi4  = (const float4*)Wi + (size_t)h * 768;
    const float4* Wf4  = (const float4*)Wf + (size_t)h * 768;

    float4 xq = qrow[tid];
    float4 xk = krow[tid];
    float4 xv = vrow[tid];

    float ai = dot4(xq, Wi4[tid]) + dot4(xk, Wi4[256 + tid]) + dot4(xv, Wi4[512 + tid]);
    float af = dot4(xq, Wf4[tid]) + dot4(xk, Wf4[256 + tid]) + dot4(xv, Wf4[512 + tid]);

    // warp h already holds the head slice in registers -> stash to smem
    if (warp == h) {
        ((float4*)q_s)[lane] = xq;
        float4 sk;
        sk.x = xk.x * rsqrtD; sk.y = xk.y * rsqrtD;
        sk.z = xk.z * rsqrtD; sk.w = xk.w * rsqrtD;
        ((float4*)k_s)[lane] = sk;
        ((float4*)v_s)[lane] = xv;
    }

    #pragma unroll
    for (int off = 16; off > 0; off >>= 1) {
        ai += __shfl_xor_sync(0xffffffffu, ai, off);
        af += __shfl_xor_sync(0xffffffffu, af, off);
    }
    if (lane == 0) { pig[warp] = ai; pfg[warp] = af; }
    __syncthreads();                                   // sync #1

    float igp = bi[h], fgp = bf[h];
    #pragma unroll
    for (int w = 0; w < 8; ++w) { igp += pig[w]; fgp += pfg[w]; }

    float log_f = fminf(fgp, 0.f) - log1pf(expf(-fabsf(fgp)));   // log sigmoid
    float m_old = maxs[bh];
    float m_new = fmaxf(igp, m_old + log_f);
    float i_g   = expf(igp - m_new);
    float f_g   = expf(log_f + m_old - m_new);

    if (tid == 0 && max_out) max_out[bh] = m_new;

    // ---- norm update + qn partials (reduction deferred to sync #2) ---------
    if (tid < HEAD) {
        float nn = fmaf(f_g, norm[(size_t)bh * HEAD + tid], i_g * k_s[tid]);
        if (norm_out) norm_out[(size_t)bh * HEAD + tid] = nn;
        float qn = q_s[tid] * nn;
        #pragma unroll
        for (int off = 16; off > 0; off >>= 1)
            qn += __shfl_xor_sync(0xffffffffu, qn, off);
        if (lane == 0) pq[warp] = qn;
    }

    // ---- main stream: rolling depth-8 pipeline over 16 rows -----------------
    float4 vreg = ((const float4*)v_s)[lane];
    float4 num  = make_float4(0.f, 0.f, 0.f, 0.f);

    #pragma unroll
    for (int i = 0; i < 16; ++i) {
        float4 c = cv[i & 7];
        if (i + 8 < 16)
            cv[i & 7] = __ldcs(cp + (i + 8) * 256);   // keep 8 rows in flight
        int r = i * 8 + warp;
        float a = i_g * k_s[r];
        float4 cn;
        cn.x = fmaf(f_g, c.x, a * vreg.x);
        cn.y = fmaf(f_g, c.y, a * vreg.y);
        cn.z = fmaf(f_g, c.z, a * vreg.z);
        cn.w = fmaf(f_g, c.w, a * vreg.w);
        if (op) __stcs(op + i * 256, cn);
        float qr = q_s[r];
        num.x = fmaf(qr, cn.x, num.x);
        num.y = fmaf(qr, cn.y, num.y);
        num.z = fmaf(qr, cn.z, num.z);
        num.w = fmaf(qr, cn.w, num.w);
    }

    // ---- numerator reduction over the 8 row-groups --------------------------
    snum[tid] = num;
    __syncthreads();                                   // sync #2 (covers pq)
    if (tid < 32) {
        float4 a = snum[tid];
        #pragma unroll
        for (int j = 1; j < 8; ++j) {
            float4 bb = snum[tid + 32 * j];
            a.x += bb.x; a.y += bb.y; a.z += bb.z; a.w += bb.w;
        }
        snum[tid] = a;   // flattened: num[0..127]
    }
    __syncthreads();                                   // sync #3

    // ---- denominator + out_pre + GN stats -----------------------------------
    float o = 0.f, so = 0.f, so2 = 0.f;
    if (tid < HEAD) {
        float qn    = pq[0] + pq[1] + pq[2] + pq[3];
        float denom = fmaxf(fabsf(qn), expf(-m_new)) + 1e-6f;
        o   = ((const float*)snum)[tid] / denom;
        so  = o;
        so2 = o * o;
    }
    #pragma unroll
    for (int off = 16; off > 0; off >>= 1) {
        so  += __shfl_xor_sync(0xffffffffu, so,  off);
        so2 += __shfl_xor_sync(0xffffffffu, so2, off);
    }
    if (tid < HEAD && lane == 0) { pm[warp] = so; pv[warp] = so2; }
    __syncthreads();                                   // sync #4

    if (tid < HEAD) {
        float mu   = (pm[0] + pm[1] + pm[2] + pm[3]) * (1.f / HEAD);
        float var  = (pv[0] + pv[1] + pv[2] + pv[3]) * (1.f / HEAD) - mu * mu;
        float rstd = rsqrtf(var + 1e-5f);
        int ch = h * HEAD + tid;
        out[(size_t)b * HIDDEN + ch] = (o - mu) * rstd * gamma[ch] + beta[ch];
    }
}

// ---------------------------------------------------------------------------
extern "C" void kernel_launch(void* const* d_in, const int* in_sizes, int n_in,
                              void* d_out, int out_size)
{
    const float* q     = (const float*)d_in[0];
    const float* k     = (const float*)d_in[1];
    const float* v     = (const float*)d_in[2];
    const float* cell  = (const float*)d_in[3];
    const float* norm  = (const float*)d_in[4];
    const float* maxs  = (const float*)d_in[5];
    const float* Wi    = (const float*)d_in[6];
    const float* bi    = (const float*)d_in[7];
    const float* Wf    = (const float*)d_in[8];
    const float* bf    = (const float*)d_in[9];
    const float* gamma = (const float*)d_in[10];
    const float* beta  = (const float*)d_in[11];

    float* out = (float*)d_out;

    const size_t OUT_N  = (size_t)BATCH * HIDDEN;                 // 524288
    const size_t CELL_N = (size_t)BATCH * HEADS * HEAD * HEAD;    // 67108864
    const size_t NORM_N = (size_t)BATCH * HEADS * HEAD;           // 524288
    const size_t MAX_N  = (size_t)BATCH * HEADS;                  // 4096

    float* cell_out = 0;
    float* norm_out = 0;
    float* max_out  = 0;
    if ((size_t)out_size >= OUT_N + CELL_N + NORM_N + MAX_N) {
        cell_out = out + OUT_N;
        norm_out = cell_out + CELL_N;
        max_out  = norm_out + NORM_N;
    }

    mlstm_fused_kernel<<<BATCH * HEADS, 256>>>(q, k, v, cell, norm, maxs,
                                               Wi, bi, Wf, bf, gamma, beta,
                                               out, cell_out, norm_out, max_out);
}

// round 12
// speedup vs baseline: 1.1181x; 1.0023x over previous
#include <cuda_runtime.h>
#include <math.h>

#define HIDDEN 1024
#define HEADS  8
#define HEAD   128
#define BATCH  512

__device__ __forceinline__ float dot4(float4 a, float4 b) {
    return a.x*b.x + a.y*b.y + a.z*b.z + a.w*b.w;
}

// 16-byte async copy to shared (L2-only): register-free prefetch.
__device__ __forceinline__ void cp_async16(void* dst_smem, const float* src) {
    unsigned int d = (unsigned int)__cvta_generic_to_shared(dst_smem);
    asm volatile("cp.async.cg.shared.global [%0], [%1], 16;" :: "r"(d), "l"(src));
}

// ---------------------------------------------------------------------------
// Fully fused gate GEMV + mLSTM step + GroupNorm. One (b,h) tile per block,
// 256 threads, 4 CTAs/SM. Round-4 streaming structure (measured best):
//   - first 8 cell-row loads issued at kernel ENTRY, hiding the gate GEMV
//   - rolling depth-8 register ring -> constant MLP=8 per warp
// Round-12 additions (critical-path diet, stream untouched):
//   - norm row prefetched via cp.async at entry (register-free), maxs/bi/bf
//     hoisted to entry -> no dependent L2/DRAM stall between gate reduction
//     and the main loop
//   - epilogue compressed: 32-thread reducer applies denominator and computes
//     GN stats in-warp -> one fewer __syncthreads, no 128-thread shuffle phase
// ---------------------------------------------------------------------------
__global__ __launch_bounds__(256, 4) void mlstm_fused_kernel(
    const float* __restrict__ q, const float* __restrict__ k,
    const float* __restrict__ v, const float* __restrict__ cell,
    const float* __restrict__ norm, const float* __restrict__ maxs,
    const float* __restrict__ Wi, const float* __restrict__ bi,
    const float* __restrict__ Wf, const float* __restrict__ bf,
    const float* __restrict__ gamma, const float* __restrict__ beta,
    float* __restrict__ out, float* __restrict__ cell_out,
    float* __restrict__ norm_out, float* __restrict__ max_out)
{
    int bh   = blockIdx.x;
    int b    = bh >> 3;
    int h    = bh & 7;
    int tid  = threadIdx.x;
    int lane = tid & 31;
    int warp = tid >> 5;

    __shared__ __align__(16) float q_s[HEAD];
    __shared__ __align__(16) float k_s[HEAD];
    __shared__ __align__(16) float v_s[HEAD];
    __shared__ __align__(16) float norm_s[HEAD];
    __shared__ float4 snum[256];
    __shared__ float pig[8], pfg[8], pq[4];
    __shared__ float s_mu, s_rstd;

    const float rsqrtD = 0.08838834764831845f;  // 1/sqrt(128)

    // ---- cell tile pointers: warp = row-group, lane = float4 column --------
    const float4* cp = (const float4*)(cell + (size_t)bh * HEAD * HEAD)
                       + warp * 32 + lane;
    float4* op = cell_out
               ? (float4*)(cell_out + (size_t)bh * HEAD * HEAD) + warp * 32 + lane
               : (float4*)0;

    // ---- entry prefetches (all independent of the gate GEMV) ---------------
    float4 cv[8];
    #pragma unroll
    for (int i = 0; i < 8; ++i)
        cv[i] = __ldcs(cp + i * 256);

    if (tid < 32) {       // norm row -> smem, register-free
        cp_async16(&norm_s[tid * 4], norm + (size_t)bh * HEAD + tid * 4);
        asm volatile("cp.async.commit_group;" ::: "memory");
    }
    float m_old = maxs[bh];                      // block-uniform scalars
    float bih   = bi[h];
    float bfh   = bf[h];

    // ---- gate pre-activations: igp/fgp = qkv_row . W[h] + b[h] -------------
    const float4* qrow = (const float4*)(q + (size_t)b * HIDDEN);
    const float4* krow = (const float4*)(k + (size_t)b * HIDDEN);
    const float4* vrow = (const float4*)(v + (size_t)b * HIDDEN);
    const float4* Wi4  = (const float4*)Wi + (size_t)h * 768;
    const float4* Wf4  = (const float4*)Wf + (size_t)h * 768;

    float4 xq = qrow[tid];
    float4 xk = krow[tid];
    float4 xv = vrow[tid];

    float ai = dot4(xq, Wi4[tid]) + dot4(xk, Wi4[256 + tid]) + dot4(xv, Wi4[512 + tid]);
    float af = dot4(xq, Wf4[tid]) + dot4(xk, Wf4[256 + tid]) + dot4(xv, Wf4[512 + tid]);

    // warp h already holds the head slice in registers -> stash to smem
    if (warp == h) {
        ((float4*)q_s)[lane] = xq;
        float4 sk;
        sk.x = xk.x * rsqrtD; sk.y = xk.y * rsqrtD;
        sk.z = xk.z * rsqrtD; sk.w = xk.w * rsqrtD;
        ((float4*)k_s)[lane] = sk;
        ((float4*)v_s)[lane] = xv;
    }

    #pragma unroll
    for (int off = 16; off > 0; off >>= 1) {
        ai += __shfl_xor_sync(0xffffffffu, ai, off);
        af += __shfl_xor_sync(0xffffffffu, af, off);
    }
    if (lane == 0) { pig[warp] = ai; pfg[warp] = af; }
    if (tid < 32)   // norm row must be in smem before sync publishes it
        asm volatile("cp.async.wait_group 0;" ::: "memory");
    __syncthreads();                                   // sync #1

    float igp = bih, fgp = bfh;
    #pragma unroll
    for (int w = 0; w < 8; ++w) { igp += pig[w]; fgp += pfg[w]; }

    float log_f = fminf(fgp, 0.f) - log1pf(expf(-fabsf(fgp)));   // log sigmoid
    float m_new = fmaxf(igp, m_old + log_f);
    float i_g   = expf(igp - m_new);
    float f_g   = expf(log_f + m_old - m_new);

    if (tid == 0 && max_out) max_out[bh] = m_new;

    // ---- norm update + qn partials (norm_s already resident) ---------------
    if (tid < HEAD) {
        float nn = fmaf(f_g, norm_s[tid], i_g * k_s[tid]);
        if (norm_out) norm_out[(size_t)bh * HEAD + tid] = nn;
        float qn = q_s[tid] * nn;
        #pragma unroll
        for (int off = 16; off > 0; off >>= 1)
            qn += __shfl_xor_sync(0xffffffffu, qn, off);
        if (lane == 0) pq[warp] = qn;
    }

    // ---- main stream: rolling depth-8 pipeline over 16 rows -----------------
    float4 vreg = ((const float4*)v_s)[lane];
    float4 num  = make_float4(0.f, 0.f, 0.f, 0.f);

    #pragma unroll
    for (int i = 0; i < 16; ++i) {
        float4 c = cv[i & 7];
        if (i + 8 < 16)
            cv[i & 7] = __ldcs(cp + (i + 8) * 256);   // keep 8 rows in flight
        int r = i * 8 + warp;
        float a = i_g * k_s[r];
        float4 cn;
        cn.x = fmaf(f_g, c.x, a * vreg.x);
        cn.y = fmaf(f_g, c.y, a * vreg.y);
        cn.z = fmaf(f_g, c.z, a * vreg.z);
        cn.w = fmaf(f_g, c.w, a * vreg.w);
        if (op) __stcs(op + i * 256, cn);
        float qr = q_s[r];
        num.x = fmaf(qr, cn.x, num.x);
        num.y = fmaf(qr, cn.y, num.y);
        num.z = fmaf(qr, cn.z, num.z);
        num.w = fmaf(qr, cn.w, num.w);
    }

    // ---- numerator reduction + denominator + GN stats, all in warp 0 --------
    snum[tid] = num;
    __syncthreads();                                   // sync #2 (covers pq)
    if (tid < 32) {
        float4 a = snum[tid];
        #pragma unroll
        for (int j = 1; j < 8; ++j) {
            float4 bb = snum[tid + 32 * j];
            a.x += bb.x; a.y += bb.y; a.z += bb.z; a.w += bb.w;
        }
        float qn    = pq[0] + pq[1] + pq[2] + pq[3];
        float denom = fmaxf(fabsf(qn), expf(-m_new)) + 1e-6f;
        float inv   = 1.f / denom;
        a.x *= inv; a.y *= inv; a.z *= inv; a.w *= inv;
        snum[tid] = a;                 // flattened: o[0..127]
        float so  = a.x + a.y + a.z + a.w;
        float so2 = a.x*a.x + a.y*a.y + a.z*a.z + a.w*a.w;
        #pragma unroll
        for (int off = 16; off > 0; off >>= 1) {
            so  += __shfl_xor_sync(0xffffffffu, so,  off);
            so2 += __shfl_xor_sync(0xffffffffu, so2, off);
        }
        if (lane == 0) {
            float mu  = so * (1.f / HEAD);
            float var = so2 * (1.f / HEAD) - mu * mu;
            s_mu   = mu;
            s_rstd = rsqrtf(var + 1e-5f);
        }
    }
    __syncthreads();                                   // sync #3

    if (tid < HEAD) {
        float o  = ((const float*)snum)[tid];
        int   ch = h * HEAD + tid;
        out[(size_t)b * HIDDEN + ch] = (o - s_mu) * s_rstd * gamma[ch] + beta[ch];
    }
}

// ---------------------------------------------------------------------------
extern "C" void kernel_launch(void* const* d_in, const int* in_sizes, int n_in,
                              void* d_out, int out_size)
{
    const float* q     = (const float*)d_in[0];
    const float* k     = (const float*)d_in[1];
    const float* v     = (const float*)d_in[2];
    const float* cell  = (const float*)d_in[3];
    const float* norm  = (const float*)d_in[4];
    const float* maxs  = (const float*)d_in[5];
    const float* Wi    = (const float*)d_in[6];
    const float* bi    = (const float*)d_in[7];
    const float* Wf    = (const float*)d_in[8];
    const float* bf    = (const float*)d_in[9];
    const float* gamma = (const float*)d_in[10];
    const float* beta  = (const float*)d_in[11];

    float* out = (float*)d_out;

    const size_t OUT_N  = (size_t)BATCH * HIDDEN;                 // 524288
    const size_t CELL_N = (size_t)BATCH * HEADS * HEAD * HEAD;    // 67108864
    const size_t NORM_N = (size_t)BATCH * HEADS * HEAD;           // 524288
    const size_t MAX_N  = (size_t)BATCH * HEADS;                  // 4096

    float* cell_out = 0;
    float* norm_out = 0;
    float* max_out  = 0;
    if ((size_t)out_size >= OUT_N + CELL_N + NORM_N + MAX_N) {
        cell_out = out + OUT_N;
        norm_out = cell_out + CELL_N;
        max_out  = norm_out + NORM_N;
    }

    mlstm_fused_kernel<<<BATCH * HEADS, 256>>>(q, k, v, cell, norm, maxs,
                                               Wi, bi, Wf, bf, gamma, beta,
                                               out, cell_out, norm_out, max_out);
}